// round 1
// baseline (speedup 1.0000x reference)
#include <cuda_runtime.h>

#define BB 2
#define NQ 20000
#define R_TOT (BB*NQ)          // 40000
#define DM 64
#define HEADS 8
#define DH 8
#define LV 5
#define PT 4
#define LIN 45109
#define NPROJ 480
#define HIDDEN 1024

// ---------------- scratch (static device memory; no allocations) -------------
__device__ float g_value[(size_t)BB*LIN*DM];     // (b, pos, h, dh)   23.1 MB
__device__ float g_proj [(size_t)R_TOT*NPROJ];   // (row, 320 off | 160 logits) 76.8 MB
__device__ float g_x    [(size_t)R_TOT*DM];      // x after LN1       10.2 MB

// ============================================================================
// Kernel A: value = dense @ Wv + bv      (90218 x 64) @ (64 x 64)
// ============================================================================
__global__ void value_proj_kernel(const float* __restrict__ X,
                                  const float* __restrict__ Wv,
                                  const float* __restrict__ bv) {
    __shared__ float Xs[64][65];
    __shared__ float Ws[64*64];
    __shared__ float bs[64];
    const int M = BB*LIN;
    const int row0 = blockIdx.x * 64;
    const int tid = threadIdx.x;

    for (int i = tid; i < 64*64; i += 256) {
        int r = i >> 6, c = i & 63;
        int gr = row0 + r;
        Xs[r][c] = (gr < M) ? X[(size_t)gr*DM + c] : 0.f;
    }
    for (int i = tid; i < 64*64; i += 256) Ws[i] = Wv[i];
    if (tid < 64) bs[tid] = bv[tid];
    __syncthreads();

    const int tq = tid >> 4, tc = tid & 15;
    const int q0 = tq*4, c0 = tc*4;
    float acc[4][4] = {};
    #pragma unroll
    for (int k = 0; k < 64; k++) {
        float4 w = *(const float4*)&Ws[k*64 + c0];
        #pragma unroll
        for (int i = 0; i < 4; i++) {
            float xv = Xs[q0+i][k];
            acc[i][0] += xv*w.x; acc[i][1] += xv*w.y;
            acc[i][2] += xv*w.z; acc[i][3] += xv*w.w;
        }
    }
    #pragma unroll
    for (int i = 0; i < 4; i++) {
        int gr = row0 + q0 + i;
        if (gr < M) {
            #pragma unroll
            for (int j = 0; j < 4; j++)
                g_value[(size_t)gr*DM + c0 + j] = acc[i][j] + bs[c0+j];
        }
    }
}

// ============================================================================
// Kernel B: proj = (q_feat + q_pos) @ [Wo | Wa] + [bo | ba]   (40000 x 480)
// ============================================================================
__global__ void qproj_kernel(const float* __restrict__ qf,
                             const float* __restrict__ qp,
                             const float* __restrict__ Wo,
                             const float* __restrict__ bo,
                             const float* __restrict__ Wa,
                             const float* __restrict__ ba) {
    __shared__ float Xs[64][65];
    __shared__ float Ws[64*64];
    __shared__ float bs[64];
    const int row0 = blockIdx.x * 64;
    const int tid = threadIdx.x;

    for (int i = tid; i < 64*64; i += 256) {
        int r = i >> 6, c = i & 63;
        size_t g = (size_t)(row0 + r)*DM + c;
        Xs[r][c] = qf[g] + qp[g];
    }

    const int tq = tid >> 4, tc = tid & 15;
    const int q0 = tq*4, c0 = tc*4;

    for (int cc = 0; cc < NPROJ; cc += 64) {
        const int cw = min(64, NPROJ - cc);
        __syncthreads();   // prev compute done (also covers Xs load on iter 0)
        for (int i = tid; i < 64*64; i += 256) {
            int k = i >> 6, j = i & 63;
            float w = 0.f;
            if (j < cw) {
                int col = cc + j;
                w = (col < 320) ? Wo[(size_t)k*320 + col]
                                : Wa[(size_t)k*160 + (col - 320)];
            }
            Ws[i] = w;
        }
        if (tid < 64) {
            float bvv = 0.f;
            if (tid < cw) {
                int col = cc + tid;
                bvv = (col < 320) ? bo[col] : ba[col - 320];
            }
            bs[tid] = bvv;
        }
        __syncthreads();

        float acc[4][4] = {};
        #pragma unroll
        for (int k = 0; k < 64; k++) {
            float4 w = *(const float4*)&Ws[k*64 + c0];
            #pragma unroll
            for (int i = 0; i < 4; i++) {
                float xv = Xs[q0+i][k];
                acc[i][0] += xv*w.x; acc[i][1] += xv*w.y;
                acc[i][2] += xv*w.z; acc[i][3] += xv*w.w;
            }
        }
        #pragma unroll
        for (int i = 0; i < 4; i++) {
            size_t rbase = (size_t)(row0 + q0 + i)*NPROJ + cc;
            #pragma unroll
            for (int j = 0; j < 4; j++)
                if (c0 + j < cw) g_proj[rbase + c0 + j] = acc[i][j] + bs[c0+j];
        }
    }
}

// ============================================================================
// Kernel C: softmax + deformable bilinear sampling + Wout + residual + LN1
// one warp per query row
// ============================================================================
__device__ __forceinline__ void sample_corner(const float* __restrict__ vb,
                                              int xi, int yi, int Wl, int Hl,
                                              float w, float* acc) {
    if (xi >= 0 && xi < Wl && yi >= 0 && yi < Hl) {
        const float4* v = (const float4*)(vb + (size_t)(yi*Wl + xi)*DM);
        float4 a = v[0], c = v[1];
        acc[0] += w*a.x; acc[1] += w*a.y; acc[2] += w*a.z; acc[3] += w*a.w;
        acc[4] += w*c.x; acc[5] += w*c.y; acc[6] += w*c.z; acc[7] += w*c.w;
    }
}

__global__ void attn_kernel(const float* __restrict__ ref,
                            const float* __restrict__ qf,
                            const float* __restrict__ Wout,
                            const float* __restrict__ bout,
                            const float* __restrict__ g1,
                            const float* __restrict__ b1) {
    __shared__ float Ws[64*64];
    __shared__ float bs[64];
    __shared__ float obuf[8][64];
    const int tid = threadIdx.x;
    for (int i = tid; i < 64*64; i += 256) Ws[i] = Wout[i];
    if (tid < 64) bs[tid] = bout[tid];
    __syncthreads();

    const int warp = tid >> 5, lane = tid & 31;
    const int r = blockIdx.x*8 + warp;          // 0..39999 exact
    const int b = r / NQ;
    const int h = lane >> 2, p = lane & 3;

    const float* pr = g_proj + (size_t)r*NPROJ;
    const float rx = ref[(size_t)r*2 + 0];
    const float ry = ref[(size_t)r*2 + 1];

    // softmax over 20 = LV*PT per head (group of 4 lanes x 5 regs)
    float lg[LV];
    #pragma unroll
    for (int l = 0; l < LV; l++) lg[l] = pr[320 + h*20 + l*4 + p];
    float m = lg[0];
    #pragma unroll
    for (int l = 1; l < LV; l++) m = fmaxf(m, lg[l]);
    m = fmaxf(m, __shfl_xor_sync(0xffffffffu, m, 1));
    m = fmaxf(m, __shfl_xor_sync(0xffffffffu, m, 2));
    float se = 0.f;
    #pragma unroll
    for (int l = 0; l < LV; l++) { lg[l] = __expf(lg[l] - m); se += lg[l]; }
    se += __shfl_xor_sync(0xffffffffu, se, 1);
    se += __shfl_xor_sync(0xffffffffu, se, 2);
    const float inv = __fdividef(1.f, se);

    const int SS[LV] = {184, 92, 46, 23, 12};
    const int ST[LV] = {0, 33856, 42320, 44436, 44965};

    float acc[8] = {0,0,0,0,0,0,0,0};
    #pragma unroll
    for (int l = 0; l < LV; l++) {
        const int Wl = SS[l], Hl = SS[l];
        const float ox = pr[((h*LV + l)*PT + p)*2 + 0];
        const float oy = pr[((h*LV + l)*PT + p)*2 + 1];
        const float aw = lg[l]*inv;
        // loc = ref + off/(W,H); then grid_sample coord = loc*size - 0.5
        const float x = rx*(float)Wl + ox - 0.5f;
        const float y = ry*(float)Hl + oy - 0.5f;
        const float x0f = floorf(x), y0f = floorf(y);
        const float wx = x - x0f, wy = y - y0f;
        const int x0 = (int)x0f, y0 = (int)y0f;
        const float w00 = (1.f-wx)*(1.f-wy)*aw;
        const float w01 = wx*(1.f-wy)*aw;
        const float w10 = (1.f-wx)*wy*aw;
        const float w11 = wx*wy*aw;
        const float* vb = g_value + ((size_t)b*LIN + ST[l])*DM + h*DH;
        sample_corner(vb, x0,   y0,   Wl, Hl, w00, acc);
        sample_corner(vb, x0+1, y0,   Wl, Hl, w01, acc);
        sample_corner(vb, x0,   y0+1, Wl, Hl, w10, acc);
        sample_corner(vb, x0+1, y0+1, Wl, Hl, w11, acc);
    }
    // reduce over the 4 point-lanes
    #pragma unroll
    for (int d = 0; d < 8; d++) {
        acc[d] += __shfl_xor_sync(0xffffffffu, acc[d], 1);
        acc[d] += __shfl_xor_sync(0xffffffffu, acc[d], 2);
    }
    if (p == 0) {
        #pragma unroll
        for (int d = 0; d < 8; d++) obuf[warp][h*DH + d] = acc[d];
    }
    __syncwarp();

    // attn_out = out_vec @ Wout + bout ; residual with q_feat ; LN1
    const int c0 = lane*2;
    float s0 = 0.f, s1 = 0.f;
    #pragma unroll
    for (int k = 0; k < 64; k++) {
        float ov = obuf[warp][k];
        s0 += ov * Ws[k*64 + c0];
        s1 += ov * Ws[k*64 + c0 + 1];
    }
    float y0v = qf[(size_t)r*DM + c0    ] + s0 + bs[c0];
    float y1v = qf[(size_t)r*DM + c0 + 1] + s1 + bs[c0+1];

    float s = y0v + y1v;
    #pragma unroll
    for (int o = 16; o > 0; o >>= 1) s += __shfl_xor_sync(0xffffffffu, s, o);
    const float mean = s * (1.f/64.f);
    float d0 = y0v - mean, d1 = y1v - mean;
    float sq = d0*d0 + d1*d1;
    #pragma unroll
    for (int o = 16; o > 0; o >>= 1) sq += __shfl_xor_sync(0xffffffffu, sq, o);
    const float rstd = rsqrtf(sq*(1.f/64.f) + 1e-5f);
    g_x[(size_t)r*DM + c0    ] = d0*rstd*g1[c0]   + b1[c0];
    g_x[(size_t)r*DM + c0 + 1] = d1*rstd*g1[c0+1] + b1[c0+1];
}

// ============================================================================
// Kernel D: FFN (64->1024 relu ->64) + residual + LN2 -> d_out
// 64 queries/block, 16 hidden chunks of 64. Dynamic smem (~66 KB).
// ============================================================================
__global__ void ffn_kernel(const float* __restrict__ W1,
                           const float* __restrict__ bff1,
                           const float* __restrict__ W2,
                           const float* __restrict__ bff2,
                           const float* __restrict__ g2,
                           const float* __restrict__ b2,
                           float* __restrict__ out) {
    extern __shared__ float sm[];
    float* Xs  = sm;                    // 64*65
    float* Hs  = Xs + 64*65;            // 64*65
    float* W1s = Hs + 64*65;            // 64*64
    float* W2s = W1s + 64*64;           // 64*64
    float* b1s = W2s + 64*64;           // 64

    const int row0 = blockIdx.x * 64;
    const int tid = threadIdx.x;

    for (int i = tid; i < 64*64; i += 256) {
        int r = i >> 6, c = i & 63;
        Xs[r*65 + c] = g_x[(size_t)(row0 + r)*DM + c];
    }

    const int tq = tid >> 4, tc = tid & 15;
    const int q0 = tq*4, c0 = tc*4;

    float bf2[4], gg[4], bb[4];
    #pragma unroll
    for (int j = 0; j < 4; j++) {
        bf2[j] = __ldg(&bff2[c0+j]);
        gg[j]  = __ldg(&g2[c0+j]);
        bb[j]  = __ldg(&b2[c0+j]);
    }

    float acc[4][4] = {};
    for (int hc = 0; hc < HIDDEN; hc += 64) {
        __syncthreads();  // prev acc done reading W2s/Hs; Xs loaded (iter 0)
        for (int i = tid; i < 64*64; i += 256) {
            int k = i >> 6, j = i & 63;
            W1s[i] = W1[(size_t)k*HIDDEN + hc + j];
        }
        if (tid < 64) b1s[tid] = bff1[hc + tid];
        __syncthreads();

        float hh[4][4] = {};
        #pragma unroll
        for (int k = 0; k < 64; k++) {
            float4 w = *(const float4*)&W1s[k*64 + c0];
            #pragma unroll
            for (int i = 0; i < 4; i++) {
                float xv = Xs[(q0+i)*65 + k];
                hh[i][0] += xv*w.x; hh[i][1] += xv*w.y;
                hh[i][2] += xv*w.z; hh[i][3] += xv*w.w;
            }
        }
        #pragma unroll
        for (int i = 0; i < 4; i++)
            #pragma unroll
            for (int j = 0; j < 4; j++)
                Hs[(q0+i)*65 + c0 + j] = fmaxf(hh[i][j] + b1s[c0+j], 0.f);

        for (int i = tid; i < 64*64; i += 256) {
            int k = i >> 6, j = i & 63;
            W2s[i] = W2[(size_t)(hc + k)*DM + j];
        }
        __syncthreads();

        #pragma unroll
        for (int k = 0; k < 64; k++) {
            float4 w = *(const float4*)&W2s[k*64 + c0];
            #pragma unroll
            for (int i = 0; i < 4; i++) {
                float hv = Hs[(q0+i)*65 + k];
                acc[i][0] += hv*w.x; acc[i][1] += hv*w.y;
                acc[i][2] += hv*w.z; acc[i][3] += hv*w.w;
            }
        }
    }

    // residual + LN2
    float y[4][4];
    float s[4], sq[4];
    #pragma unroll
    for (int i = 0; i < 4; i++) {
        s[i] = 0.f;
        #pragma unroll
        for (int j = 0; j < 4; j++) {
            y[i][j] = Xs[(q0+i)*65 + c0 + j] + acc[i][j] + bf2[j];
            s[i] += y[i][j];
        }
    }
    #pragma unroll
    for (int i = 0; i < 4; i++) {
        #pragma unroll
        for (int o = 8; o > 0; o >>= 1)
            s[i] += __shfl_xor_sync(0xffffffffu, s[i], o);   // 16-thread group
        s[i] *= (1.f/64.f);
    }
    #pragma unroll
    for (int i = 0; i < 4; i++) {
        sq[i] = 0.f;
        #pragma unroll
        for (int j = 0; j < 4; j++) {
            y[i][j] -= s[i];
            sq[i] += y[i][j]*y[i][j];
        }
    }
    #pragma unroll
    for (int i = 0; i < 4; i++) {
        #pragma unroll
        for (int o = 8; o > 0; o >>= 1)
            sq[i] += __shfl_xor_sync(0xffffffffu, sq[i], o);
        const float rstd = rsqrtf(sq[i]*(1.f/64.f) + 1e-5f);
        const size_t rbase = (size_t)(row0 + q0 + i)*DM;
        #pragma unroll
        for (int j = 0; j < 4; j++)
            out[rbase + c0 + j] = y[i][j]*rstd*gg[j] + bb[j];
    }
}

// ============================================================================
extern "C" void kernel_launch(void* const* d_in, const int* in_sizes, int n_in,
                              void* d_out, int out_size) {
    const float* q_feat = (const float*)d_in[0];
    const float* dense  = (const float*)d_in[1];
    const float* ref    = (const float*)d_in[2];
    const float* q_pos  = (const float*)d_in[3];
    // d_in[4] spatial_shapes (int64), d_in[5] level_start_index (int64): constants, hardcoded
    const float* Wv   = (const float*)d_in[6];
    const float* bv   = (const float*)d_in[7];
    const float* Wo   = (const float*)d_in[8];
    const float* bo   = (const float*)d_in[9];
    const float* Wa   = (const float*)d_in[10];
    const float* ba   = (const float*)d_in[11];
    const float* Wout = (const float*)d_in[12];
    const float* bout = (const float*)d_in[13];
    const float* g1   = (const float*)d_in[14];
    const float* b1   = (const float*)d_in[15];
    const float* W1   = (const float*)d_in[16];
    const float* bff1 = (const float*)d_in[17];
    const float* W2   = (const float*)d_in[18];
    const float* bff2 = (const float*)d_in[19];
    const float* g2   = (const float*)d_in[20];
    const float* b2   = (const float*)d_in[21];
    float* out = (float*)d_out;

    const int smem_d = (64*65 + 64*65 + 64*64 + 64*64 + 64) * (int)sizeof(float);
    cudaFuncSetAttribute(ffn_kernel, cudaFuncAttributeMaxDynamicSharedMemorySize, smem_d);

    value_proj_kernel<<<(BB*LIN + 63)/64, 256>>>(dense, Wv, bv);
    qproj_kernel<<<R_TOT/64, 256>>>(q_feat, q_pos, Wo, bo, Wa, ba);
    attn_kernel<<<R_TOT/8, 256>>>(ref, q_feat, Wout, bout, g1, b1);
    ffn_kernel<<<R_TOT/64, 256, smem_d>>>(W1, bff1, W2, bff2, g2, b2, out);
}

// round 2
// speedup vs baseline: 1.4315x; 1.4315x over previous
#include <cuda_runtime.h>
#include <cstdint>

#define BB 2
#define NQ 20000
#define R_TOT (BB*NQ)          // 40000
#define DM 64
#define HEADS 8
#define DH 8
#define LV 5
#define PT 4
#define LIN 45109
#define NPROJ 480
#define HIDDEN 1024
#define FP 68                  // smem pitch (floats): 68 % 32 == 4 -> conflict-free ldmatrix

// ---------------- scratch (static device memory; no allocations) -------------
__device__ float g_value[(size_t)BB*LIN*DM];     // (b, pos, h, dh)   23.1 MB
__device__ float g_proj [(size_t)R_TOT*NPROJ];   // (row, 320 off | 160 logits) 76.8 MB
__device__ float g_x    [(size_t)R_TOT*DM];      // x after LN1       10.2 MB

// ---------------- mma/ldmatrix helpers ---------------------------------------
__device__ __forceinline__ float to_tf32(float x) {
    uint32_t u;
    asm("cvt.rna.tf32.f32 %0, %1;" : "=r"(u) : "f"(x));
    return __uint_as_float(u);
}

__device__ __forceinline__ void ldm_x4(uint32_t& a0, uint32_t& a1, uint32_t& a2, uint32_t& a3,
                                       uint32_t addr) {
    asm volatile("ldmatrix.sync.aligned.m8n8.x4.shared.b16 {%0,%1,%2,%3}, [%4];"
                 : "=r"(a0), "=r"(a1), "=r"(a2), "=r"(a3) : "r"(addr));
}

__device__ __forceinline__ void ldm_x2(uint32_t& b0, uint32_t& b1, uint32_t addr) {
    asm volatile("ldmatrix.sync.aligned.m8n8.x2.shared.b16 {%0,%1}, [%2];"
                 : "=r"(b0), "=r"(b1) : "r"(addr));
}

__device__ __forceinline__ void mma_tf32(float c[4],
                                         uint32_t a0, uint32_t a1, uint32_t a2, uint32_t a3,
                                         uint32_t b0, uint32_t b1) {
    asm volatile("mma.sync.aligned.m16n8k8.row.col.f32.tf32.tf32.f32 "
                 "{%0,%1,%2,%3}, {%4,%5,%6,%7}, {%8,%9}, {%0,%1,%2,%3};"
                 : "+f"(c[0]), "+f"(c[1]), "+f"(c[2]), "+f"(c[3])
                 : "r"(a0), "r"(a1), "r"(a2), "r"(a3), "r"(b0), "r"(b1));
}

// ============================================================================
// Kernel A: value = dense @ Wv + bv      (90218 x 64) @ (64 x 64)
// ============================================================================
__global__ void value_proj_kernel(const float* __restrict__ X,
                                  const float* __restrict__ Wv,
                                  const float* __restrict__ bv) {
    __shared__ float Xs[64][65];
    __shared__ float Ws[64*64];
    __shared__ float bs[64];
    const int M = BB*LIN;
    const int row0 = blockIdx.x * 64;
    const int tid = threadIdx.x;

    for (int i = tid; i < 64*64; i += 256) {
        int r = i >> 6, c = i & 63;
        int gr = row0 + r;
        Xs[r][c] = (gr < M) ? X[(size_t)gr*DM + c] : 0.f;
    }
    for (int i = tid; i < 64*64; i += 256) Ws[i] = Wv[i];
    if (tid < 64) bs[tid] = bv[tid];
    __syncthreads();

    const int tq = tid >> 4, tc = tid & 15;
    const int q0 = tq*4, c0 = tc*4;
    float acc[4][4] = {};
    #pragma unroll
    for (int k = 0; k < 64; k++) {
        float4 w = *(const float4*)&Ws[k*64 + c0];
        #pragma unroll
        for (int i = 0; i < 4; i++) {
            float xv = Xs[q0+i][k];
            acc[i][0] += xv*w.x; acc[i][1] += xv*w.y;
            acc[i][2] += xv*w.z; acc[i][3] += xv*w.w;
        }
    }
    #pragma unroll
    for (int i = 0; i < 4; i++) {
        int gr = row0 + q0 + i;
        if (gr < M) {
            #pragma unroll
            for (int j = 0; j < 4; j++)
                g_value[(size_t)gr*DM + c0 + j] = acc[i][j] + bs[c0+j];
        }
    }
}

// ============================================================================
// Kernel B: proj = (q_feat + q_pos) @ [Wo | Wa] + [bo | ba]   (40000 x 480)
// ============================================================================
__global__ void qproj_kernel(const float* __restrict__ qf,
                             const float* __restrict__ qp,
                             const float* __restrict__ Wo,
                             const float* __restrict__ bo,
                             const float* __restrict__ Wa,
                             const float* __restrict__ ba) {
    __shared__ float Xs[64][65];
    __shared__ float Ws[64*64];
    __shared__ float bs[64];
    const int row0 = blockIdx.x * 64;
    const int tid = threadIdx.x;

    for (int i = tid; i < 64*64; i += 256) {
        int r = i >> 6, c = i & 63;
        size_t g = (size_t)(row0 + r)*DM + c;
        Xs[r][c] = qf[g] + qp[g];
    }

    const int tq = tid >> 4, tc = tid & 15;
    const int q0 = tq*4, c0 = tc*4;

    for (int cc = 0; cc < NPROJ; cc += 64) {
        const int cw = min(64, NPROJ - cc);
        __syncthreads();
        for (int i = tid; i < 64*64; i += 256) {
            int k = i >> 6, j = i & 63;
            float w = 0.f;
            if (j < cw) {
                int col = cc + j;
                w = (col < 320) ? Wo[(size_t)k*320 + col]
                                : Wa[(size_t)k*160 + (col - 320)];
            }
            Ws[i] = w;
        }
        if (tid < 64) {
            float bvv = 0.f;
            if (tid < cw) {
                int col = cc + tid;
                bvv = (col < 320) ? bo[col] : ba[col - 320];
            }
            bs[tid] = bvv;
        }
        __syncthreads();

        float acc[4][4] = {};
        #pragma unroll
        for (int k = 0; k < 64; k++) {
            float4 w = *(const float4*)&Ws[k*64 + c0];
            #pragma unroll
            for (int i = 0; i < 4; i++) {
                float xv = Xs[q0+i][k];
                acc[i][0] += xv*w.x; acc[i][1] += xv*w.y;
                acc[i][2] += xv*w.z; acc[i][3] += xv*w.w;
            }
        }
        #pragma unroll
        for (int i = 0; i < 4; i++) {
            size_t rbase = (size_t)(row0 + q0 + i)*NPROJ + cc;
            #pragma unroll
            for (int j = 0; j < 4; j++)
                if (c0 + j < cw) g_proj[rbase + c0 + j] = acc[i][j] + bs[c0+j];
        }
    }
}

// ============================================================================
// Kernel C: softmax + deformable bilinear sampling + Wout + residual + LN1
// ============================================================================
__device__ __forceinline__ void sample_corner(const float* __restrict__ vb,
                                              int xi, int yi, int Wl, int Hl,
                                              float w, float* acc) {
    if (xi >= 0 && xi < Wl && yi >= 0 && yi < Hl) {
        const float4* v = (const float4*)(vb + (size_t)(yi*Wl + xi)*DM);
        float4 a = v[0], c = v[1];
        acc[0] += w*a.x; acc[1] += w*a.y; acc[2] += w*a.z; acc[3] += w*a.w;
        acc[4] += w*c.x; acc[5] += w*c.y; acc[6] += w*c.z; acc[7] += w*c.w;
    }
}

__global__ void attn_kernel(const float* __restrict__ ref,
                            const float* __restrict__ qf,
                            const float* __restrict__ Wout,
                            const float* __restrict__ bout,
                            const float* __restrict__ g1,
                            const float* __restrict__ b1) {
    __shared__ float Ws[64*64];
    __shared__ float bs[64];
    __shared__ float obuf[8][64];
    const int tid = threadIdx.x;
    for (int i = tid; i < 64*64; i += 256) Ws[i] = Wout[i];
    if (tid < 64) bs[tid] = bout[tid];
    __syncthreads();

    const int warp = tid >> 5, lane = tid & 31;
    const int r = blockIdx.x*8 + warp;
    const int b = r / NQ;
    const int h = lane >> 2, p = lane & 3;

    const float* pr = g_proj + (size_t)r*NPROJ;
    const float rx = ref[(size_t)r*2 + 0];
    const float ry = ref[(size_t)r*2 + 1];

    float lg[LV];
    #pragma unroll
    for (int l = 0; l < LV; l++) lg[l] = pr[320 + h*20 + l*4 + p];
    float m = lg[0];
    #pragma unroll
    for (int l = 1; l < LV; l++) m = fmaxf(m, lg[l]);
    m = fmaxf(m, __shfl_xor_sync(0xffffffffu, m, 1));
    m = fmaxf(m, __shfl_xor_sync(0xffffffffu, m, 2));
    float se = 0.f;
    #pragma unroll
    for (int l = 0; l < LV; l++) { lg[l] = __expf(lg[l] - m); se += lg[l]; }
    se += __shfl_xor_sync(0xffffffffu, se, 1);
    se += __shfl_xor_sync(0xffffffffu, se, 2);
    const float inv = __fdividef(1.f, se);

    const int SS[LV] = {184, 92, 46, 23, 12};
    const int ST[LV] = {0, 33856, 42320, 44436, 44965};

    float acc[8] = {0,0,0,0,0,0,0,0};
    #pragma unroll
    for (int l = 0; l < LV; l++) {
        const int Wl = SS[l], Hl = SS[l];
        const float ox = pr[((h*LV + l)*PT + p)*2 + 0];
        const float oy = pr[((h*LV + l)*PT + p)*2 + 1];
        const float aw = lg[l]*inv;
        const float x = rx*(float)Wl + ox - 0.5f;
        const float y = ry*(float)Hl + oy - 0.5f;
        const float x0f = floorf(x), y0f = floorf(y);
        const float wx = x - x0f, wy = y - y0f;
        const int x0 = (int)x0f, y0 = (int)y0f;
        const float w00 = (1.f-wx)*(1.f-wy)*aw;
        const float w01 = wx*(1.f-wy)*aw;
        const float w10 = (1.f-wx)*wy*aw;
        const float w11 = wx*wy*aw;
        const float* vb = g_value + ((size_t)b*LIN + ST[l])*DM + h*DH;
        sample_corner(vb, x0,   y0,   Wl, Hl, w00, acc);
        sample_corner(vb, x0+1, y0,   Wl, Hl, w01, acc);
        sample_corner(vb, x0,   y0+1, Wl, Hl, w10, acc);
        sample_corner(vb, x0+1, y0+1, Wl, Hl, w11, acc);
    }
    #pragma unroll
    for (int d = 0; d < 8; d++) {
        acc[d] += __shfl_xor_sync(0xffffffffu, acc[d], 1);
        acc[d] += __shfl_xor_sync(0xffffffffu, acc[d], 2);
    }
    if (p == 0) {
        #pragma unroll
        for (int d = 0; d < 8; d++) obuf[warp][h*DH + d] = acc[d];
    }
    __syncwarp();

    const int c0 = lane*2;
    float s0 = 0.f, s1 = 0.f;
    #pragma unroll
    for (int k = 0; k < 64; k++) {
        float ov = obuf[warp][k];
        s0 += ov * Ws[k*64 + c0];
        s1 += ov * Ws[k*64 + c0 + 1];
    }
    float y0v = qf[(size_t)r*DM + c0    ] + s0 + bs[c0];
    float y1v = qf[(size_t)r*DM + c0 + 1] + s1 + bs[c0+1];

    float s = y0v + y1v;
    #pragma unroll
    for (int o = 16; o > 0; o >>= 1) s += __shfl_xor_sync(0xffffffffu, s, o);
    const float mean = s * (1.f/64.f);
    float d0 = y0v - mean, d1 = y1v - mean;
    float sq = d0*d0 + d1*d1;
    #pragma unroll
    for (int o = 16; o > 0; o >>= 1) sq += __shfl_xor_sync(0xffffffffu, sq, o);
    const float rstd = rsqrtf(sq*(1.f/64.f) + 1e-5f);
    g_x[(size_t)r*DM + c0    ] = d0*rstd*g1[c0]   + b1[c0];
    g_x[(size_t)r*DM + c0 + 1] = d1*rstd*g1[c0+1] + b1[c0+1];
}

// ============================================================================
// Kernel D: FFN via tf32 mma.sync  (128 queries/block, 8 warps)
//   GEMM1: H = relu(X @ W1c + b1c)   (128x64x64 per chunk)
//   GEMM2: acc += H @ W2c            (128x64x64 per chunk), 16 chunks
//   then residual + LN2 -> d_out
// ============================================================================
__global__ void __launch_bounds__(256, 2)
ffn_kernel(const float* __restrict__ W1,
           const float* __restrict__ bff1,
           const float* __restrict__ W2,
           const float* __restrict__ bff2,
           const float* __restrict__ g2v,
           const float* __restrict__ b2v,
           float* __restrict__ out) {
    extern __shared__ float sm[];
    float* Xs   = sm;                    // 128*FP  (fp32 — residual-exact)
    float* Hs   = Xs  + 128*FP;          // 128*FP  (tf32-rounded)
    float* W1s  = Hs  + 128*FP;          // 64*FP   layout [n][k], tf32
    float* W2s  = W1s + 64*FP;           // 64*FP   layout [n][k], tf32
    float* b1s  = W2s + 64*FP;           // 64
    float* pars = b1s + 64;              // 192: bff2 | g2 | b2

    const int tid  = threadIdx.x;
    const int row0 = blockIdx.x * 128;

    // X tile (fp32, float4)
    for (int i = tid; i < 128*16; i += 256) {
        int r = i >> 4, c = (i & 15) * 4;
        int gr = row0 + r;
        float4 v = (gr < R_TOT) ? *(const float4*)&g_x[(size_t)gr*DM + c]
                                : make_float4(0.f, 0.f, 0.f, 0.f);
        *(float4*)&Xs[r*FP + c] = v;
    }
    if (tid < 64) {
        pars[tid]       = bff2[tid];
        pars[64 + tid]  = g2v[tid];
        pars[128 + tid] = b2v[tid];
    }

    const int lane = tid & 31, warp = tid >> 5;
    const int r0 = warp * 16;
    const int g  = lane >> 2, tg = lane & 3;

    // ldmatrix per-lane addresses
    const int arow = (lane & 7) + ((lane >> 3) & 1) * 8;
    const int acol = (lane >> 4) * 4;
    const int brow = lane & 7;
    const int bcol = ((lane >> 3) & 1) * 4;

    const uint32_t XsA = (uint32_t)__cvta_generic_to_shared(&Xs[(r0 + arow)*FP + acol]);
    const uint32_t HsA = (uint32_t)__cvta_generic_to_shared(&Hs[(r0 + arow)*FP + acol]);
    const uint32_t W1B = (uint32_t)__cvta_generic_to_shared(&W1s[brow*FP + bcol]);
    const uint32_t W2B = (uint32_t)__cvta_generic_to_shared(&W2s[brow*FP + bcol]);

    float accC[8][4] = {};

    // W fill indices: thread owns output col n, k-range [k0, k0+16)
    const int wn = tid >> 2;
    const int wk0 = (tid & 3) * 16;

    for (int hc = 0; hc < HIDDEN; hc += 64) {
        __syncthreads();   // prev GEMM2 done reading W2s/Hs (and Xs/pars ready on iter 0)
        {
            const float* w1p = W1 + (size_t)wk0*HIDDEN + hc + wn;
            const float* w2p = W2 + (size_t)(hc + wk0)*DM + wn;
            float buf[16];
            #pragma unroll
            for (int t = 0; t < 16; t++) buf[t] = to_tf32(w1p[(size_t)t*HIDDEN]);
            #pragma unroll
            for (int j = 0; j < 4; j++)
                *(float4*)&W1s[wn*FP + wk0 + j*4] = *(float4*)&buf[j*4];
            #pragma unroll
            for (int t = 0; t < 16; t++) buf[t] = to_tf32(w2p[(size_t)t*DM]);
            #pragma unroll
            for (int j = 0; j < 4; j++)
                *(float4*)&W2s[wn*FP + wk0 + j*4] = *(float4*)&buf[j*4];
            if (tid < 64) b1s[tid] = bff1[hc + tid];
        }
        __syncthreads();

        // GEMM1
        float c1[8][4] = {};
        #pragma unroll
        for (int ks = 0; ks < 8; ks++) {
            uint32_t a0, a1, a2, a3;
            ldm_x4(a0, a1, a2, a3, XsA + ks*32);
            #pragma unroll
            for (int nf = 0; nf < 8; nf++) {
                uint32_t b0, b1;
                ldm_x2(b0, b1, W1B + nf*(FP*32) + ks*32);
                mma_tf32(c1[nf], a0, a1, a2, a3, b0, b1);
            }
        }

        // relu + bias -> Hs (tf32), own rows only
        #pragma unroll
        for (int nf = 0; nf < 8; nf++) {
            int cc = nf*8 + 2*tg;
            float bb0 = b1s[cc], bb1 = b1s[cc+1];
            float2 hA = make_float2(to_tf32(fmaxf(c1[nf][0] + bb0, 0.f)),
                                    to_tf32(fmaxf(c1[nf][1] + bb1, 0.f)));
            float2 hB = make_float2(to_tf32(fmaxf(c1[nf][2] + bb0, 0.f)),
                                    to_tf32(fmaxf(c1[nf][3] + bb1, 0.f)));
            *(float2*)&Hs[(r0 + g)*FP + cc]     = hA;
            *(float2*)&Hs[(r0 + 8 + g)*FP + cc] = hB;
        }
        __syncwarp();   // warp reads back only its own 16 rows

        // GEMM2
        #pragma unroll
        for (int ks = 0; ks < 8; ks++) {
            uint32_t a0, a1, a2, a3;
            ldm_x4(a0, a1, a2, a3, HsA + ks*32);
            #pragma unroll
            for (int nf = 0; nf < 8; nf++) {
                uint32_t b0, b1;
                ldm_x2(b0, b1, W2B + nf*(FP*32) + ks*32);
                mma_tf32(accC[nf], a0, a1, a2, a3, b0, b1);
            }
        }
    }

    // ---- epilogue: residual + LN2 ----
    float sA = 0.f, sB = 0.f;
    #pragma unroll
    for (int nf = 0; nf < 8; nf++) {
        int cc = nf*8 + 2*tg;
        accC[nf][0] += Xs[(r0 + g)*FP + cc]       + pars[cc];
        accC[nf][1] += Xs[(r0 + g)*FP + cc + 1]   + pars[cc+1];
        accC[nf][2] += Xs[(r0 + 8 + g)*FP + cc]   + pars[cc];
        accC[nf][3] += Xs[(r0 + 8 + g)*FP + cc+1] + pars[cc+1];
        sA += accC[nf][0] + accC[nf][1];
        sB += accC[nf][2] + accC[nf][3];
    }
    sA += __shfl_xor_sync(0xffffffffu, sA, 1);
    sA += __shfl_xor_sync(0xffffffffu, sA, 2);
    sB += __shfl_xor_sync(0xffffffffu, sB, 1);
    sB += __shfl_xor_sync(0xffffffffu, sB, 2);
    const float mA = sA * (1.f/64.f), mB = sB * (1.f/64.f);

    float qA = 0.f, qB = 0.f;
    #pragma unroll
    for (int nf = 0; nf < 8; nf++) {
        accC[nf][0] -= mA; accC[nf][1] -= mA;
        accC[nf][2] -= mB; accC[nf][3] -= mB;
        qA += accC[nf][0]*accC[nf][0] + accC[nf][1]*accC[nf][1];
        qB += accC[nf][2]*accC[nf][2] + accC[nf][3]*accC[nf][3];
    }
    qA += __shfl_xor_sync(0xffffffffu, qA, 1);
    qA += __shfl_xor_sync(0xffffffffu, qA, 2);
    qB += __shfl_xor_sync(0xffffffffu, qB, 1);
    qB += __shfl_xor_sync(0xffffffffu, qB, 2);
    const float rA = rsqrtf(qA*(1.f/64.f) + 1e-5f);
    const float rB = rsqrtf(qB*(1.f/64.f) + 1e-5f);

    const int grA = row0 + r0 + g;
    const int grB = grA + 8;
    #pragma unroll
    for (int nf = 0; nf < 8; nf++) {
        int cc = nf*8 + 2*tg;
        float gg0 = pars[64+cc], gg1 = pars[64+cc+1];
        float bb0 = pars[128+cc], bb1 = pars[128+cc+1];
        if (grA < R_TOT)
            *(float2*)&out[(size_t)grA*DM + cc] =
                make_float2(accC[nf][0]*rA*gg0 + bb0, accC[nf][1]*rA*gg1 + bb1);
        if (grB < R_TOT)
            *(float2*)&out[(size_t)grB*DM + cc] =
                make_float2(accC[nf][2]*rB*gg0 + bb0, accC[nf][3]*rB*gg1 + bb1);
    }
}

// ============================================================================
extern "C" void kernel_launch(void* const* d_in, const int* in_sizes, int n_in,
                              void* d_out, int out_size) {
    const float* q_feat = (const float*)d_in[0];
    const float* dense  = (const float*)d_in[1];
    const float* ref    = (const float*)d_in[2];
    const float* q_pos  = (const float*)d_in[3];
    const float* Wv   = (const float*)d_in[6];
    const float* bv   = (const float*)d_in[7];
    const float* Wo   = (const float*)d_in[8];
    const float* bo   = (const float*)d_in[9];
    const float* Wa   = (const float*)d_in[10];
    const float* ba   = (const float*)d_in[11];
    const float* Wout = (const float*)d_in[12];
    const float* bout = (const float*)d_in[13];
    const float* g1   = (const float*)d_in[14];
    const float* b1   = (const float*)d_in[15];
    const float* W1   = (const float*)d_in[16];
    const float* bff1 = (const float*)d_in[17];
    const float* W2   = (const float*)d_in[18];
    const float* bff2 = (const float*)d_in[19];
    const float* g2   = (const float*)d_in[20];
    const float* b2   = (const float*)d_in[21];
    float* out = (float*)d_out;

    const int smem_d = (128*FP*2 + 64*FP*2 + 64 + 192) * (int)sizeof(float);
    static bool attr_set = false;
    if (!attr_set) {
        cudaFuncSetAttribute(ffn_kernel, cudaFuncAttributeMaxDynamicSharedMemorySize, smem_d);
        attr_set = true;
    }

    value_proj_kernel<<<(BB*LIN + 63)/64, 256>>>(dense, Wv, bv);
    qproj_kernel<<<R_TOT/64, 256>>>(q_feat, q_pos, Wo, bo, Wa, ba);
    attn_kernel<<<R_TOT/8, 256>>>(ref, q_feat, Wout, bout, g1, b1);
    ffn_kernel<<<(R_TOT + 127)/128, 256, smem_d>>>(W1, bff1, W2, bff2, g2, b2, out);
}